// round 3
// baseline (speedup 1.0000x reference)
#include <cuda_runtime.h>

#define Bn 16
#define Qn 64
#define Kn 1024
#define Dn 256
#define Hn 128

// Scratch (device globals: no allocation allowed)
__device__ float g_qp[Bn*Qn*Hn];       // projected queries  [B,Q,H]
__device__ float g_kp[Bn*Kn*Hn];       // projected keys     [B,K,H]
__device__ float g_attn[Bn*Qn*Kn];     // scores -> exp(s-m) in place [B,Q,K]
__device__ float g_inv[Bn*Qn];         // 1/sum_exp per row
#define KS 8
#define OKS (Kn/KS)                    // 128 k per split
__device__ float g_part[KS*Bn*Qn*Dn];  // output partials [KS][B,Q,D]

// ---------- packed f32x2 helpers (Blackwell) ----------
__device__ __forceinline__ unsigned long long pack2(float x, float y){
    unsigned long long r; asm("mov.b64 %0, {%1,%2};" : "=l"(r) : "f"(x), "f"(y)); return r;
}
__device__ __forceinline__ unsigned long long fma2(unsigned long long a, unsigned long long b, unsigned long long c){
    unsigned long long d; asm("fma.rn.f32x2 %0, %1, %2, %3;" : "=l"(d) : "l"(a), "l"(b), "l"(c)); return d;
}
__device__ __forceinline__ void unpack2(unsigned long long v, float& lo, float& hi){
    asm("mov.b64 {%0,%1}, %2;" : "=f"(lo), "=f"(hi) : "l"(v));
}
__device__ __forceinline__ float tanh_fast(float x){
    float y; asm("tanh.approx.f32 %0, %1;" : "=f"(y) : "f"(x)); return y;
}

// ---------------- projection (q and k fused into one launch) ----------------
#define PR 32    // rows per block
#define PT 128   // threads (= Hn)
#define XS 36    // padded smem row stride (floats); 144B, 16B-aligned
#define QBLOCKS ((Bn*Qn)/PR)   // 32
#define KBLOCKS ((Bn*Kn)/PR)   // 512

__global__ __launch_bounds__(PT) void proj_kernel(const float* __restrict__ Xq,
                                                  const float* __restrict__ Wq,
                                                  const float* __restrict__ Xk,
                                                  const float* __restrict__ Wk){
    __shared__ float xs[Dn*XS];   // X tile transposed: xs[d][r]
    const float* X; const float* W; float* out; int row0;
    if (blockIdx.x < QBLOCKS){ X = Xq; W = Wq; out = g_qp; row0 = blockIdx.x * PR; }
    else                     { X = Xk; W = Wk; out = g_kp; row0 = (blockIdx.x - QBLOCKS) * PR; }
    const int t = threadIdx.x;

    for (int i = t; i < PR*Dn; i += PT){
        int r = i >> 8;          // /256
        int d = i & (Dn-1);
        xs[d*XS + r] = X[(row0 + r)*Dn + d];
    }
    __syncthreads();

    unsigned long long acc[PR/2];
#pragma unroll
    for (int i = 0; i < PR/2; i++) acc[i] = 0ull;

    float w = W[t];                                  // prefetch pipeline head
#pragma unroll 4
    for (int d = 0; d < Dn; d++){
        float wn = W[((d+1) & (Dn-1))*Hn + t];       // branchless wrap prefetch
        unsigned long long w2 = pack2(w, w);
        const ulonglong2* xp = reinterpret_cast<const ulonglong2*>(&xs[d*XS]);
#pragma unroll
        for (int m = 0; m < PR/4; m++){
            ulonglong2 xv = xp[m];                   // warp-uniform LDS.128 broadcast
            acc[2*m]   = fma2(w2, xv.x, acc[2*m]);
            acc[2*m+1] = fma2(w2, xv.y, acc[2*m+1]);
        }
        w = wn;
    }
#pragma unroll
    for (int i = 0; i < PR/2; i++){
        float lo, hi; unpack2(acc[i], lo, hi);
        out[(row0 + 2*i    )*Hn + t] = lo;
        out[(row0 + 2*i + 1)*Hn + t] = hi;
    }
}

// --------- scores: s[b,q,k] = sum_h w_v[h] * tanh(qp[b,q,h] + kp[b,k,h]) ---------
#define SKT 32
#define SQT 16
#define ST  256

__global__ __launch_bounds__(ST) void score_kernel(const float* __restrict__ wv,
                                                   const int* __restrict__ vlen){
    const int b  = blockIdx.z;
    const int v  = vlen[b];
    const int k0 = blockIdx.x * SKT;
    if (k0 >= v) return;
    const int kmax = min(SKT, v - k0);

    __shared__ float ks[SKT*Hn];     // swizzled kp tile
    __shared__ float qs[SQT*Hn];     // q tile (plain)
    __shared__ float ws[Hn];
    const int t = threadIdx.x;
    if (t < Hn) ws[t] = wv[t];

    const float* kpb = g_kp + (size_t)(b*Kn + k0)*Hn;
    for (int i = t; i < SKT*Hn; i += ST){
        int j = i >> 7, h = i & 127;
        int sidx = j*Hn + ((((h>>2) ^ (j & 7))) << 2) + (h & 3);
        ks[sidx] = kpb[i];
    }
    const int q0 = blockIdx.y * SQT;
    const float* qpb = g_qp + (size_t)(b*Qn + q0)*Hn;
    for (int i = t; i < SQT*Hn; i += ST) qs[i] = qpb[i];
    __syncthreads();

    const int j  = t & 31;        // k lane
    const int qh = t >> 5;        // q phase 0..7 (uniform within warp)
    const int jx = j & 7;
    float* sc = g_attn + (size_t)(b*Qn + q0)*Kn;

#pragma unroll
    for (int qi = 0; qi < SQT/8; qi++){
        const int q = qi*8 + qh;
        float acc0 = 0.f, acc1 = 0.f;
#pragma unroll 8
        for (int c = 0; c < Hn/4; c++){
            float4 kv = *reinterpret_cast<const float4*>(&ks[j*Hn + ((c ^ jx) << 2)]);
            float4 qv = *reinterpret_cast<const float4*>(&qs[q*Hn + (c << 2)]); // broadcast
            float4 w4 = *reinterpret_cast<const float4*>(&ws[c << 2]);
            acc0 += w4.x * tanh_fast(qv.x + kv.x);
            acc1 += w4.y * tanh_fast(qv.y + kv.y);
            acc0 += w4.z * tanh_fast(qv.z + kv.z);
            acc1 += w4.w * tanh_fast(qv.w + kv.w);
        }
        if (j < kmax) sc[q*Kn + k0 + j] = acc0 + acc1;
    }
}

// ------------- softexp: row -> exp(row - max); store 1/sum to g_inv -------------
#define SMT 128
__global__ __launch_bounds__(SMT) void softexp_kernel(const int* __restrict__ vlen){
    const int bq = blockIdx.x;
    const int b = bq >> 6;
    const int v = vlen[b];
    float4* row4 = reinterpret_cast<float4*>(g_attn + (size_t)bq*Kn);
    const int t = threadIdx.x;

    float4 x[2];
    float m = -1e30f;
#pragma unroll
    for (int i = 0; i < 2; i++){
        float4 a = row4[t + i*SMT];
        int k = 4*(t + i*SMT);
        a.x = (k+0 < v) ? a.x : -1e30f;
        a.y = (k+1 < v) ? a.y : -1e30f;
        a.z = (k+2 < v) ? a.z : -1e30f;
        a.w = (k+3 < v) ? a.w : -1e30f;
        x[i] = a;
        m = fmaxf(m, fmaxf(fmaxf(a.x, a.y), fmaxf(a.z, a.w)));
    }
    __shared__ float redm[4];
#pragma unroll
    for (int o = 16; o > 0; o >>= 1) m = fmaxf(m, __shfl_xor_sync(0xffffffffu, m, o));
    if ((t & 31) == 0) redm[t >> 5] = m;
    __syncthreads();
    m = fmaxf(fmaxf(redm[0], redm[1]), fmaxf(redm[2], redm[3]));

    float s = 0.f;
#pragma unroll
    for (int i = 0; i < 2; i++){
        x[i].x = __expf(x[i].x - m); x[i].y = __expf(x[i].y - m);
        x[i].z = __expf(x[i].z - m); x[i].w = __expf(x[i].w - m);
        s += (x[i].x + x[i].y) + (x[i].z + x[i].w);
    }
#pragma unroll
    for (int o = 16; o > 0; o >>= 1) s += __shfl_xor_sync(0xffffffffu, s, o);
    __shared__ float reds[4];
    if ((t & 31) == 0) reds[t >> 5] = s;
    __syncthreads();
    s = reds[0] + reds[1] + reds[2] + reds[3];

#pragma unroll
    for (int i = 0; i < 2; i++) row4[t + i*SMT] = x[i];   // masked lanes hold exp(-big)=0
    if (t == 0) g_inv[bq] = __fdividef(1.f, s);
}

// --------- out partials: part[kz][b,q,d] = sum_{k in slice, k<v} e[b,q,k]*V[b,k,d] ---------
#define OQT 16
#define OT  128   // d2 lanes: thread owns d = {2t, 2t+1}
#define ASTR 20   // padded attn-tile row stride (floats): 80B, 16B-aligned, 4-way STS max

__global__ __launch_bounds__(OT) void outpart_kernel(const float* __restrict__ V,
                                                     const int* __restrict__ vlen){
    const int qt = blockIdx.x;    // 0..3
    const int kz = blockIdx.y;    // 0..KS-1
    const int b  = blockIdx.z;
    const int v  = vlen[b];
    const int k0 = kz * OKS;
    const int q0 = qt * OQT;
    const int t  = threadIdx.x;
    float* part = g_part + ((size_t)kz*Bn*Qn + b*Qn + q0)*Dn;

    if (k0 >= v){
        float2 z = make_float2(0.f, 0.f);
#pragma unroll
        for (int r = 0; r < OQT; r++)
            reinterpret_cast<float2*>(part + r*Dn)[t] = z;
        return;
    }
    const int kmax = min(OKS, v - k0);

    __shared__ float as[OKS*ASTR];   // e tile: as[k*ASTR + q]
    const float* attb = g_attn + (size_t)(b*Qn + q0)*Kn + k0;
    for (int i = t; i < OQT*OKS; i += OT){
        int q = i >> 7, k = i & (OKS-1);       // lanes: consecutive k, coalesced LDG
        if (k < kmax) as[k*ASTR + q] = attb[q*Kn + k];
    }
    __syncthreads();

    const float2* V2 = reinterpret_cast<const float2*>(V + ((size_t)b*Kn + k0)*Dn);
    unsigned long long accA[OQT/2];   // (q2r,q2r+1) x d0
    unsigned long long accB[OQT/2];   // (q2r,q2r+1) x d1
#pragma unroll
    for (int r = 0; r < OQT/2; r++){ accA[r] = 0ull; accB[r] = 0ull; }

#pragma unroll 4
    for (int k = 0; k < kmax; k++){
        float2 vv = V2[(size_t)k*(Dn/2) + t];
        unsigned long long v0 = pack2(vv.x, vv.x);
        unsigned long long v1 = pack2(vv.y, vv.y);
        const ulonglong2* ap = reinterpret_cast<const ulonglong2*>(&as[k*ASTR]); // broadcast
#pragma unroll
        for (int g = 0; g < 4; g++){
            ulonglong2 ag = ap[g];    // q = 4g..4g+3 as two f32x2 pairs
            accA[2*g]   = fma2(ag.x, v0, accA[2*g]);
            accB[2*g]   = fma2(ag.x, v1, accB[2*g]);
            accA[2*g+1] = fma2(ag.y, v0, accA[2*g+1]);
            accB[2*g+1] = fma2(ag.y, v1, accB[2*g+1]);
        }
    }

#pragma unroll
    for (int r = 0; r < OQT/2; r++){
        float fa, fb, ga, gb;
        unpack2(accA[r], fa, fb);   // fa: q=2r,d0   fb: q=2r+1,d0
        unpack2(accB[r], ga, gb);   // ga: q=2r,d1   gb: q=2r+1,d1
        reinterpret_cast<float2*>(part + (2*r  )*Dn)[t] = make_float2(fa, ga);
        reinterpret_cast<float2*>(part + (2*r+1)*Dn)[t] = make_float2(fb, gb);
    }
}

// ---------------- reduce: out = inv_sum * sum_s part[s] ----------------
#define RT 128
#define NOUT4 ((Bn*Qn*Dn)/4)   // 65536 float4

__global__ __launch_bounds__(RT) void reduce_kernel(float* __restrict__ out){
    const int i4 = blockIdx.x * RT + threadIdx.x;
    const float4* p = reinterpret_cast<const float4*>(g_part);
    float4 s = p[i4];
#pragma unroll
    for (int z = 1; z < KS; z++){
        float4 x = p[(size_t)z*NOUT4 + i4];
        s.x += x.x; s.y += x.y; s.z += x.z; s.w += x.w;
    }
    const float inv = g_inv[i4 >> 6];    // 64 float4 per (b,q) row
    s.x *= inv; s.y *= inv; s.z *= inv; s.w *= inv;
    reinterpret_cast<float4*>(out)[i4] = s;
}

// ---------------- launch ----------------
extern "C" void kernel_launch(void* const* d_in, const int* in_sizes, int n_in,
                              void* d_out, int out_size){
    const float* queries = (const float*)d_in[0];
    const float* keys    = (const float*)d_in[1];
    const float* values  = (const float*)d_in[2];
    const int*   vlen    = (const int*)  d_in[3];
    const float* W_q     = (const float*)d_in[4];
    const float* W_k     = (const float*)d_in[5];
    const float* w_v     = (const float*)d_in[6];
    float* out = (float*)d_out;

    proj_kernel<<<QBLOCKS + KBLOCKS, PT>>>(queries, W_q, keys, W_k);        // 544 blocks
    score_kernel<<<dim3(Kn/SKT, Qn/SQT, Bn), ST>>>(w_v, vlen);              // 2048 blocks
    softexp_kernel<<<Bn*Qn, SMT>>>(vlen);                                   // 1024 blocks
    outpart_kernel<<<dim3(Qn/OQT, KS, Bn), OT>>>(values, vlen);             // 512 blocks
    reduce_kernel<<<NOUT4/RT, RT>>>(out);                                   // 512 blocks
}

// round 4
// speedup vs baseline: 1.0417x; 1.0417x over previous
#include <cuda_runtime.h>

#define Bn 16
#define Qn 64
#define Kn 1024
#define Dn 256
#define Hn 128

// Scratch (device globals: no allocation allowed)
__device__ float g_qp[Bn*Qn*Hn];       // projected queries  [B,Q,H]
__device__ float g_kp[Bn*Kn*Hn];       // projected keys     [B,K,H]
__device__ float g_attn[Bn*Qn*Kn];     // scores -> exp(s-m) in place [B,Q,K]
__device__ float g_inv[Bn*Qn];         // 1/sum_exp per row
#define KS 16
#define OKS (Kn/KS)                    // 64 k per split
__device__ float g_part[KS*Bn*Qn*Dn];  // output partials [KS][B,Q,D]

// ---------- packed f32x2 helpers (Blackwell) ----------
__device__ __forceinline__ unsigned long long pack2(float x, float y){
    unsigned long long r; asm("mov.b64 %0, {%1,%2};" : "=l"(r) : "f"(x), "f"(y)); return r;
}
__device__ __forceinline__ unsigned long long fma2(unsigned long long a, unsigned long long b, unsigned long long c){
    unsigned long long d; asm("fma.rn.f32x2 %0, %1, %2, %3;" : "=l"(d) : "l"(a), "l"(b), "l"(c)); return d;
}
__device__ __forceinline__ void unpack2(unsigned long long v, float& lo, float& hi){
    asm("mov.b64 {%0,%1}, %2;" : "=f"(lo), "=f"(hi) : "l"(v));
}
__device__ __forceinline__ float tanh_fast(float x){
    float y; asm("tanh.approx.f32 %0, %1;" : "=f"(y) : "f"(x)); return y;
}

// ---------------- projection (q and k fused into one launch) ----------------
#define PR 32    // rows per block
#define PT 128   // threads (= Hn)
#define XS 36    // padded smem row stride (floats); 144B, 16B-aligned
#define QBLOCKS ((Bn*Qn)/PR)   // 32
#define KBLOCKS ((Bn*Kn)/PR)   // 512

__global__ __launch_bounds__(PT) void proj_kernel(const float* __restrict__ Xq,
                                                  const float* __restrict__ Wq,
                                                  const float* __restrict__ Xk,
                                                  const float* __restrict__ Wk){
    __shared__ float xs[Dn*XS];   // X tile transposed: xs[d][r]
    const float* X; const float* W; float* out; int row0;
    if (blockIdx.x < QBLOCKS){ X = Xq; W = Wq; out = g_qp; row0 = blockIdx.x * PR; }
    else                     { X = Xk; W = Wk; out = g_kp; row0 = (blockIdx.x - QBLOCKS) * PR; }
    const int t = threadIdx.x;

    for (int i = t; i < PR*Dn; i += PT){
        int r = i >> 8;          // /256
        int d = i & (Dn-1);
        xs[d*XS + r] = X[(row0 + r)*Dn + d];
    }
    __syncthreads();

    unsigned long long acc[PR/2];
#pragma unroll
    for (int i = 0; i < PR/2; i++) acc[i] = 0ull;

    float w = W[t];                                  // prefetch pipeline head
#pragma unroll 4
    for (int d = 0; d < Dn; d++){
        float wn = W[((d+1) & (Dn-1))*Hn + t];       // branchless wrap prefetch
        unsigned long long w2 = pack2(w, w);
        const ulonglong2* xp = reinterpret_cast<const ulonglong2*>(&xs[d*XS]);
#pragma unroll
        for (int m = 0; m < PR/4; m++){
            ulonglong2 xv = xp[m];                   // warp-uniform LDS.128 broadcast
            acc[2*m]   = fma2(w2, xv.x, acc[2*m]);
            acc[2*m+1] = fma2(w2, xv.y, acc[2*m+1]);
        }
        w = wn;
    }
#pragma unroll
    for (int i = 0; i < PR/2; i++){
        float lo, hi; unpack2(acc[i], lo, hi);
        out[(row0 + 2*i    )*Hn + t] = lo;
        out[(row0 + 2*i + 1)*Hn + t] = hi;
    }
}

// --------- scores: s[b,q,k] = sum_h w_v[h] * tanh(qp[b,q,h] + kp[b,k,h]) ---------
#define SKT 32
#define SQT 16
#define ST  256

__global__ __launch_bounds__(ST) void score_kernel(const float* __restrict__ wv,
                                                   const int* __restrict__ vlen){
    const int b  = blockIdx.z;
    const int v  = vlen[b];
    const int k0 = blockIdx.x * SKT;
    if (k0 >= v) return;
    const int kmax = min(SKT, v - k0);

    __shared__ float ks[SKT*Hn];     // swizzled kp tile
    __shared__ float qs[SQT*Hn];     // q tile (plain)
    __shared__ float ws[Hn];
    const int t = threadIdx.x;
    if (t < Hn) ws[t] = wv[t];

    const float* kpb = g_kp + (size_t)(b*Kn + k0)*Hn;
    for (int i = t; i < SKT*Hn; i += ST){
        int j = i >> 7, h = i & 127;
        int sidx = j*Hn + ((((h>>2) ^ (j & 7))) << 2) + (h & 3);
        ks[sidx] = kpb[i];
    }
    const int q0 = blockIdx.y * SQT;
    const float* qpb = g_qp + (size_t)(b*Qn + q0)*Hn;
    for (int i = t; i < SQT*Hn; i += ST) qs[i] = qpb[i];
    __syncthreads();

    const int j  = t & 31;        // k lane
    const int qh = t >> 5;        // q phase 0..7 (uniform within warp)
    const int jx = j & 7;
    float* sc = g_attn + (size_t)(b*Qn + q0)*Kn;

#pragma unroll
    for (int qi = 0; qi < SQT/8; qi++){
        const int q = qi*8 + qh;
        float acc0 = 0.f, acc1 = 0.f;
#pragma unroll 8
        for (int c = 0; c < Hn/4; c++){
            float4 kv = *reinterpret_cast<const float4*>(&ks[j*Hn + ((c ^ jx) << 2)]);
            float4 qv = *reinterpret_cast<const float4*>(&qs[q*Hn + (c << 2)]); // broadcast
            float4 w4 = *reinterpret_cast<const float4*>(&ws[c << 2]);
            acc0 += w4.x * tanh_fast(qv.x + kv.x);
            acc1 += w4.y * tanh_fast(qv.y + kv.y);
            acc0 += w4.z * tanh_fast(qv.z + kv.z);
            acc1 += w4.w * tanh_fast(qv.w + kv.w);
        }
        if (j < kmax) sc[q*Kn + k0 + j] = acc0 + acc1;
    }
}

// ------------- softexp: row -> exp(row - max); store 1/sum to g_inv -------------
#define SMT 128
__global__ __launch_bounds__(SMT) void softexp_kernel(const int* __restrict__ vlen){
    const int bq = blockIdx.x;
    const int b = bq >> 6;
    const int v = vlen[b];
    float4* row4 = reinterpret_cast<float4*>(g_attn + (size_t)bq*Kn);
    const int t = threadIdx.x;

    float4 x[2];
    float m = -1e30f;
#pragma unroll
    for (int i = 0; i < 2; i++){
        float4 a = row4[t + i*SMT];
        int k = 4*(t + i*SMT);
        a.x = (k+0 < v) ? a.x : -1e30f;
        a.y = (k+1 < v) ? a.y : -1e30f;
        a.z = (k+2 < v) ? a.z : -1e30f;
        a.w = (k+3 < v) ? a.w : -1e30f;
        x[i] = a;
        m = fmaxf(m, fmaxf(fmaxf(a.x, a.y), fmaxf(a.z, a.w)));
    }
    __shared__ float redm[4];
#pragma unroll
    for (int o = 16; o > 0; o >>= 1) m = fmaxf(m, __shfl_xor_sync(0xffffffffu, m, o));
    if ((t & 31) == 0) redm[t >> 5] = m;
    __syncthreads();
    m = fmaxf(fmaxf(redm[0], redm[1]), fmaxf(redm[2], redm[3]));

    float s = 0.f;
#pragma unroll
    for (int i = 0; i < 2; i++){
        x[i].x = __expf(x[i].x - m); x[i].y = __expf(x[i].y - m);
        x[i].z = __expf(x[i].z - m); x[i].w = __expf(x[i].w - m);
        s += (x[i].x + x[i].y) + (x[i].z + x[i].w);
    }
#pragma unroll
    for (int o = 16; o > 0; o >>= 1) s += __shfl_xor_sync(0xffffffffu, s, o);
    __shared__ float reds[4];
    if ((t & 31) == 0) reds[t >> 5] = s;
    __syncthreads();
    s = reds[0] + reds[1] + reds[2] + reds[3];

#pragma unroll
    for (int i = 0; i < 2; i++) row4[t + i*SMT] = x[i];   // masked lanes hold exp(-big)=0
    if (t == 0) g_inv[bq] = __fdividef(1.f, s);
}

// --------- out partials: part[kz][b,q,d] = sum_{k in slice, k<v} e[b,q,k]*V[b,k,d] ---------
// Split blocks with k0 >= v write NOTHING; reduce_kernel skips those splits.
#define OQT 16
#define OT  128   // d2 lanes: thread owns d = {2t, 2t+1}
#define ASTR 20   // padded attn-tile row stride (floats): 80B, 16B-aligned
#define PF  8     // V prefetch depth (register ring)

__global__ __launch_bounds__(OT) void outpart_kernel(const float* __restrict__ V,
                                                     const int* __restrict__ vlen){
    const int qt = blockIdx.x;    // 0..3
    const int kz = blockIdx.y;    // 0..KS-1
    const int b  = blockIdx.z;
    const int v  = vlen[b];
    const int k0 = kz * OKS;
    if (k0 >= v) return;                      // dead split: reduce skips it
    const int q0 = qt * OQT;
    const int t  = threadIdx.x;
    const int kmax = min(OKS, v - k0);

    __shared__ float as[OKS*ASTR];   // e tile: as[k*ASTR + q]
    const float* attb = g_attn + (size_t)(b*Qn + q0)*Kn + k0;
    for (int i = t; i < OQT*OKS; i += OT){
        int q = i >> 6, k = i & (OKS-1);       // lanes: consecutive k, coalesced LDG
        as[k*ASTR + q] = (k < kmax) ? attb[q*Kn + k] : 0.f;
    }
    __syncthreads();

    const float2* Vt = reinterpret_cast<const float2*>(V + ((size_t)b*Kn + k0)*Dn) + t;
    unsigned long long accA[OQT/2];   // (q2r,q2r+1) x d0
    unsigned long long accB[OQT/2];   // (q2r,q2r+1) x d1
#pragma unroll
    for (int r = 0; r < OQT/2; r++){ accA[r] = 0ull; accB[r] = 0ull; }

    // register ring: PF V loads in flight (slice rows always valid memory)
    float2 vbuf[PF];
#pragma unroll
    for (int p = 0; p < PF; p++) vbuf[p] = Vt[(size_t)p*(Dn/2)];

#pragma unroll 8
    for (int k = 0; k < kmax; k++){
        float2 vv = vbuf[k & (PF-1)];
        int kp = k + PF;
        if (kp < OKS) vbuf[k & (PF-1)] = Vt[(size_t)kp*(Dn/2)];
        unsigned long long v0 = pack2(vv.x, vv.x);
        unsigned long long v1 = pack2(vv.y, vv.y);
        const ulonglong2* ap = reinterpret_cast<const ulonglong2*>(&as[k*ASTR]); // broadcast
#pragma unroll
        for (int g = 0; g < 4; g++){
            ulonglong2 ag = ap[g];    // q = 4g..4g+3 as two f32x2 pairs
            accA[2*g]   = fma2(ag.x, v0, accA[2*g]);
            accB[2*g]   = fma2(ag.x, v1, accB[2*g]);
            accA[2*g+1] = fma2(ag.y, v0, accA[2*g+1]);
            accB[2*g+1] = fma2(ag.y, v1, accB[2*g+1]);
        }
    }

    float* part = g_part + ((size_t)kz*Bn*Qn + b*Qn + q0)*Dn;
#pragma unroll
    for (int r = 0; r < OQT/2; r++){
        float fa, fb, ga, gb;
        unpack2(accA[r], fa, fb);   // fa: q=2r,d0   fb: q=2r+1,d0
        unpack2(accB[r], ga, gb);   // ga: q=2r,d1   gb: q=2r+1,d1
        reinterpret_cast<float2*>(part + (2*r  )*Dn)[t] = make_float2(fa, ga);
        reinterpret_cast<float2*>(part + (2*r+1)*Dn)[t] = make_float2(fb, gb);
    }
}

// ---------------- reduce: out = inv_sum * sum_{live splits} part[s] ----------------
#define RT 128
#define NOUT4 ((Bn*Qn*Dn)/4)   // 65536 float4

__global__ __launch_bounds__(RT) void reduce_kernel(const int* __restrict__ vlen,
                                                    float* __restrict__ out){
    const int i4 = blockIdx.x * RT + threadIdx.x;
    const int b  = i4 >> 12;                 // 4096 float4 per batch
    const int nz = (vlen[b] + OKS - 1) >> 6; // live splits (>=1)
    const float4* p = reinterpret_cast<const float4*>(g_part);
    float4 s = p[i4];
#pragma unroll 4
    for (int z = 1; z < nz; z++){
        float4 x = p[(size_t)z*NOUT4 + i4];
        s.x += x.x; s.y += x.y; s.z += x.z; s.w += x.w;
    }
    const float inv = g_inv[i4 >> 6];    // 64 float4 per (b,q) row
    s.x *= inv; s.y *= inv; s.z *= inv; s.w *= inv;
    reinterpret_cast<float4*>(out)[i4] = s;
}

// ---------------- launch ----------------
extern "C" void kernel_launch(void* const* d_in, const int* in_sizes, int n_in,
                              void* d_out, int out_size){
    const float* queries = (const float*)d_in[0];
    const float* keys    = (const float*)d_in[1];
    const float* values  = (const float*)d_in[2];
    const int*   vlen    = (const int*)  d_in[3];
    const float* W_q     = (const float*)d_in[4];
    const float* W_k     = (const float*)d_in[5];
    const float* w_v     = (const float*)d_in[6];
    float* out = (float*)d_out;

    proj_kernel<<<QBLOCKS + KBLOCKS, PT>>>(queries, W_q, keys, W_k);        // 544 blocks
    score_kernel<<<dim3(Kn/SKT, Qn/SQT, Bn), ST>>>(w_v, vlen);              // 2048 blocks
    softexp_kernel<<<Bn*Qn, SMT>>>(vlen);                                   // 1024 blocks
    outpart_kernel<<<dim3(Qn/OQT, KS, Bn), OT>>>(values, vlen);             // 1024 blocks
    reduce_kernel<<<NOUT4/RT, RT>>>(vlen, out);                             // 512 blocks
}

// round 5
// speedup vs baseline: 1.0660x; 1.0233x over previous
#include <cuda_runtime.h>

#define Bn 16
#define Qn 64
#define Kn 1024
#define Dn 256
#define Hn 128

// Scratch (device globals: no allocation allowed)
__device__ float g_qp[Bn*Qn*Hn];       // projected queries  [B,Q,H]
__device__ float g_kp[Bn*Kn*Hn];       // projected keys     [B,K,H]
__device__ float g_attn[Bn*Qn*Kn];     // scores -> exp(s-m) in place [B,Q,K]
__device__ float g_inv[Bn*Qn];         // 1/sum_exp per row
#define KS 16
#define OKS (Kn/KS)                    // 64 k per split
__device__ float g_part[KS*Bn*Qn*Dn];  // output partials [KS][B,Q,D]

// ---------- packed f32x2 helpers (Blackwell) ----------
__device__ __forceinline__ unsigned long long pack2(float x, float y){
    unsigned long long r; asm("mov.b64 %0, {%1,%2};" : "=l"(r) : "f"(x), "f"(y)); return r;
}
__device__ __forceinline__ unsigned long long fma2(unsigned long long a, unsigned long long b, unsigned long long c){
    unsigned long long d; asm("fma.rn.f32x2 %0, %1, %2, %3;" : "=l"(d) : "l"(a), "l"(b), "l"(c)); return d;
}
__device__ __forceinline__ void unpack2(unsigned long long v, float& lo, float& hi){
    asm("mov.b64 {%0,%1}, %2;" : "=f"(lo), "=f"(hi) : "l"(v));
}
__device__ __forceinline__ float tanh_fast(float x){
    float y; asm("tanh.approx.f32 %0, %1;" : "=f"(y) : "f"(x)); return y;
}

// ---------------- projection (q and k fused into one launch) ----------------
#define PR 32    // rows per block
#define PT 128   // threads (= Hn)
#define XS 36    // padded smem row stride (floats); 144B, 16B-aligned
#define QBLOCKS ((Bn*Qn)/PR)   // 32
#define KBLOCKS ((Bn*Kn)/PR)   // 512

__global__ __launch_bounds__(PT) void proj_kernel(const float* __restrict__ Xq,
                                                  const float* __restrict__ Wq,
                                                  const float* __restrict__ Xk,
                                                  const float* __restrict__ Wk){
    __shared__ float xs[Dn*XS];   // X tile transposed: xs[d][r]
    const float* X; const float* W; float* out; int row0;
    if (blockIdx.x < QBLOCKS){ X = Xq; W = Wq; out = g_qp; row0 = blockIdx.x * PR; }
    else                     { X = Xk; W = Wk; out = g_kp; row0 = (blockIdx.x - QBLOCKS) * PR; }
    const int t = threadIdx.x;

    for (int i = t; i < PR*Dn; i += PT){
        int r = i >> 8;          // /256
        int d = i & (Dn-1);
        xs[d*XS + r] = X[(row0 + r)*Dn + d];
    }
    __syncthreads();

    unsigned long long acc[PR/2];
#pragma unroll
    for (int i = 0; i < PR/2; i++) acc[i] = 0ull;

#pragma unroll 2
    for (int d = 0; d < Dn; d++){
        float w = W[d*Hn + t];                       // coalesced, L1-resident
        unsigned long long w2 = pack2(w, w);
        const ulonglong2* xp = reinterpret_cast<const ulonglong2*>(&xs[d*XS]);
#pragma unroll
        for (int m = 0; m < PR/4; m++){
            ulonglong2 xv = xp[m];                   // warp-uniform LDS.128 broadcast
            acc[2*m]   = fma2(w2, xv.x, acc[2*m]);
            acc[2*m+1] = fma2(w2, xv.y, acc[2*m+1]);
        }
    }
#pragma unroll
    for (int i = 0; i < PR/2; i++){
        float lo, hi; unpack2(acc[i], lo, hi);
        out[(row0 + 2*i    )*Hn + t] = lo;
        out[(row0 + 2*i + 1)*Hn + t] = hi;
    }
}

// --------- scores: s[b,q,k] = sum_h w_v[h] * tanh(qp[b,q,h] + kp[b,k,h]) ---------
#define SKT 32
#define SQT 16
#define ST  256

__global__ __launch_bounds__(ST) void score_kernel(const float* __restrict__ wv,
                                                   const int* __restrict__ vlen){
    const int b  = blockIdx.z;
    const int v  = vlen[b];
    const int k0 = blockIdx.x * SKT;
    if (k0 >= v) return;
    const int kmax = min(SKT, v - k0);

    __shared__ float ks[SKT*Hn];     // swizzled kp tile
    __shared__ float qs[SQT*Hn];     // q tile (plain)
    __shared__ float ws[Hn];
    const int t = threadIdx.x;
    if (t < Hn) ws[t] = wv[t];

    const float* kpb = g_kp + (size_t)(b*Kn + k0)*Hn;
    for (int i = t; i < SKT*Hn; i += ST){
        int j = i >> 7, h = i & 127;
        int sidx = j*Hn + ((((h>>2) ^ (j & 7))) << 2) + (h & 3);
        ks[sidx] = kpb[i];
    }
    const int q0 = blockIdx.y * SQT;
    const float* qpb = g_qp + (size_t)(b*Qn + q0)*Hn;
    for (int i = t; i < SQT*Hn; i += ST) qs[i] = qpb[i];
    __syncthreads();

    const int j  = t & 31;        // k lane
    const int qh = t >> 5;        // q phase 0..7 (uniform within warp)
    const int jx = j & 7;
    float* sc = g_attn + (size_t)(b*Qn + q0)*Kn;

#pragma unroll
    for (int qi = 0; qi < SQT/8; qi++){
        const int q = qi*8 + qh;
        float acc0 = 0.f, acc1 = 0.f;
#pragma unroll 8
        for (int c = 0; c < Hn/4; c++){
            float4 kv = *reinterpret_cast<const float4*>(&ks[j*Hn + ((c ^ jx) << 2)]);
            float4 qv = *reinterpret_cast<const float4*>(&qs[q*Hn + (c << 2)]); // broadcast
            float4 w4 = *reinterpret_cast<const float4*>(&ws[c << 2]);
            acc0 += w4.x * tanh_fast(qv.x + kv.x);
            acc1 += w4.y * tanh_fast(qv.y + kv.y);
            acc0 += w4.z * tanh_fast(qv.z + kv.z);
            acc1 += w4.w * tanh_fast(qv.w + kv.w);
        }
        if (j < kmax) sc[q*Kn + k0 + j] = acc0 + acc1;
    }
}

// ------------- softexp: row -> exp(row - max); store 1/sum to g_inv -------------
#define SMT 128
__global__ __launch_bounds__(SMT) void softexp_kernel(const int* __restrict__ vlen){
    const int bq = blockIdx.x;
    const int b = bq >> 6;
    const int v = vlen[b];
    float4* row4 = reinterpret_cast<float4*>(g_attn + (size_t)bq*Kn);
    const int t = threadIdx.x;

    float4 x[2];
    float m = -1e30f;
#pragma unroll
    for (int i = 0; i < 2; i++){
        float4 a = row4[t + i*SMT];
        int k = 4*(t + i*SMT);
        a.x = (k+0 < v) ? a.x : -1e30f;
        a.y = (k+1 < v) ? a.y : -1e30f;
        a.z = (k+2 < v) ? a.z : -1e30f;
        a.w = (k+3 < v) ? a.w : -1e30f;
        x[i] = a;
        m = fmaxf(m, fmaxf(fmaxf(a.x, a.y), fmaxf(a.z, a.w)));
    }
    __shared__ float redm[4];
#pragma unroll
    for (int o = 16; o > 0; o >>= 1) m = fmaxf(m, __shfl_xor_sync(0xffffffffu, m, o));
    if ((t & 31) == 0) redm[t >> 5] = m;
    __syncthreads();
    m = fmaxf(fmaxf(redm[0], redm[1]), fmaxf(redm[2], redm[3]));

    float s = 0.f;
#pragma unroll
    for (int i = 0; i < 2; i++){
        x[i].x = __expf(x[i].x - m); x[i].y = __expf(x[i].y - m);
        x[i].z = __expf(x[i].z - m); x[i].w = __expf(x[i].w - m);
        s += (x[i].x + x[i].y) + (x[i].z + x[i].w);
    }
#pragma unroll
    for (int o = 16; o > 0; o >>= 1) s += __shfl_xor_sync(0xffffffffu, s, o);
    __shared__ float reds[4];
    if ((t & 31) == 0) reds[t >> 5] = s;
    __syncthreads();
    s = reds[0] + reds[1] + reds[2] + reds[3];

#pragma unroll
    for (int i = 0; i < 2; i++) row4[t + i*SMT] = x[i];   // masked lanes hold exp(-big)=0
    if (t == 0) g_inv[bq] = __fdividef(1.f, s);
}

// --------- out partials: part[kz][b,q,d] = sum_{k in slice, k<v} e[b,q,k]*V[b,k,d] ---------
// Dead splits (k0 >= v) write NOTHING; reduce_kernel skips them.
// Compute loop is a branch-free fixed 64 iterations: exps beyond kmax are 0 in
// SMEM, and V rows k0..k0+63 are always valid memory (k0+63 <= 1023).
#define OQT 16
#define OT  128   // d2 lanes: thread owns d = {2t, 2t+1}
#define ASTR 20   // padded attn-tile row stride (floats): 80B, 16B-aligned

__global__ __launch_bounds__(OT, 6) void outpart_kernel(const float* __restrict__ V,
                                                        const int* __restrict__ vlen){
    const int qt = blockIdx.x;    // 0..3
    const int kz = blockIdx.y;    // 0..KS-1
    const int b  = blockIdx.z;
    const int v  = vlen[b];
    const int k0 = kz * OKS;
    if (k0 >= v) return;                      // dead split: reduce skips it
    const int q0 = qt * OQT;
    const int t  = threadIdx.x;
    const int kmax = min(OKS, v - k0);

    __shared__ float as[OKS*ASTR];   // e tile: as[k*ASTR + q]
    const float* attb = g_attn + (size_t)(b*Qn + q0)*Kn + k0;
    for (int i = t; i < OQT*OKS; i += OT){
        int q = i >> 6, k = i & (OKS-1);       // lanes: consecutive k, coalesced LDG
        as[k*ASTR + q] = (k < kmax) ? attb[q*Kn + k] : 0.f;
    }
    __syncthreads();

    const float2* Vt = reinterpret_cast<const float2*>(V + ((size_t)b*Kn + k0)*Dn) + t;
    unsigned long long accA[OQT/2];   // (q2r,q2r+1) x d0
    unsigned long long accB[OQT/2];   // (q2r,q2r+1) x d1
#pragma unroll
    for (int r = 0; r < OQT/2; r++){ accA[r] = 0ull; accB[r] = 0ull; }

#pragma unroll 8
    for (int k = 0; k < OKS; k++){             // fixed trip, no branches
        float2 vv = Vt[(size_t)k*(Dn/2)];
        unsigned long long v0 = pack2(vv.x, vv.x);
        unsigned long long v1 = pack2(vv.y, vv.y);
        const ulonglong2* ap = reinterpret_cast<const ulonglong2*>(&as[k*ASTR]); // broadcast
#pragma unroll
        for (int g = 0; g < 4; g++){
            ulonglong2 ag = ap[g];    // q = 4g..4g+3 as two f32x2 pairs
            accA[2*g]   = fma2(ag.x, v0, accA[2*g]);
            accB[2*g]   = fma2(ag.x, v1, accB[2*g]);
            accA[2*g+1] = fma2(ag.y, v0, accA[2*g+1]);
            accB[2*g+1] = fma2(ag.y, v1, accB[2*g+1]);
        }
    }

    float* part = g_part + ((size_t)kz*Bn*Qn + b*Qn + q0)*Dn;
#pragma unroll
    for (int r = 0; r < OQT/2; r++){
        float fa, fb, ga, gb;
        unpack2(accA[r], fa, fb);   // fa: q=2r,d0   fb: q=2r+1,d0
        unpack2(accB[r], ga, gb);   // ga: q=2r,d1   gb: q=2r+1,d1
        reinterpret_cast<float2*>(part + (2*r  )*Dn)[t] = make_float2(fa, ga);
        reinterpret_cast<float2*>(part + (2*r+1)*Dn)[t] = make_float2(fb, gb);
    }
}

// ---------------- reduce: out = inv_sum * sum_{live splits} part[s] ----------------
#define RT 128
#define NOUT4 ((Bn*Qn*Dn)/4)   // 65536 float4

__global__ __launch_bounds__(RT) void reduce_kernel(const int* __restrict__ vlen,
                                                    float* __restrict__ out){
    const int i4 = blockIdx.x * RT + threadIdx.x;
    const int b  = i4 >> 12;                 // 4096 float4 per batch
    const int nz = (vlen[b] + OKS - 1) >> 6; // live splits (>=1)
    const float4* p = reinterpret_cast<const float4*>(g_part);
    float4 s = p[i4];
#pragma unroll 4
    for (int z = 1; z < nz; z++){
        float4 x = p[(size_t)z*NOUT4 + i4];
        s.x += x.x; s.y += x.y; s.z += x.z; s.w += x.w;
    }
    const float inv = g_inv[i4 >> 6];    // 64 float4 per (b,q) row
    s.x *= inv; s.y *= inv; s.z *= inv; s.w *= inv;
    reinterpret_cast<float4*>(out)[i4] = s;
}

// ---------------- launch ----------------
extern "C" void kernel_launch(void* const* d_in, const int* in_sizes, int n_in,
                              void* d_out, int out_size){
    const float* queries = (const float*)d_in[0];
    const float* keys    = (const float*)d_in[1];
    const float* values  = (const float*)d_in[2];
    const int*   vlen    = (const int*)  d_in[3];
    const float* W_q     = (const float*)d_in[4];
    const float* W_k     = (const float*)d_in[5];
    const float* w_v     = (const float*)d_in[6];
    float* out = (float*)d_out;

    proj_kernel<<<QBLOCKS + KBLOCKS, PT>>>(queries, W_q, keys, W_k);        // 544 blocks
    score_kernel<<<dim3(Kn/SKT, Qn/SQT, Bn), ST>>>(w_v, vlen);              // 2048 blocks
    softexp_kernel<<<Bn*Qn, SMT>>>(vlen);                                   // 1024 blocks
    outpart_kernel<<<dim3(Qn/OQT, KS, Bn), OT>>>(values, vlen);             // 1024 blocks
    reduce_kernel<<<NOUT4/RT, RT>>>(vlen, out);                             // 512 blocks
}